// round 1
// baseline (speedup 1.0000x reference)
#include <cuda_runtime.h>
#include <math.h>

// ---------------- problem constants ----------------
#define NB   8
#define LSEQ 1024      // latents length
#define SSEQ 2048      // tokens length after conv (10240/5)
#define DIM  512
#define TOKD 256
#define KIN  1280      // 256*5 flattened conv reduction

// ---------------- scratch (device globals; no allocation allowed) ----------------
__device__ __align__(256) float g_Wc  [DIM * KIN];
__device__ __align__(256) float g_tok [NB * SSEQ * DIM];
__device__ __align__(256) float g_Rlat[NB * LSEQ * DIM];
__device__ __align__(256) float g_Rtok[NB * SSEQ * DIM];
__device__ __align__(256) float g_Vlat[NB * LSEQ * DIM];
__device__ __align__(256) float g_Vtok[NB * SSEQ * DIM];
__device__ __align__(256) float g_S   [NB * LSEQ * SSEQ];   // score matrix A
__device__ __align__(256) float g_rmax[NB * LSEQ];
__device__ __align__(256) float g_rinv[NB * LSEQ];
__device__ __align__(256) float g_cmax[NB * SSEQ];
__device__ __align__(256) float g_cinv[NB * SSEQ];

// ---------------- tiling config ----------------
#define BM 128
#define BN 128
#define BK 8
// 256 threads, each computes 8x8

__device__ __forceinline__ void mma_step(const float (*As)[BM], const float (*Bs)[BN],
                                         float acc[8][8], int ty, int tx) {
#pragma unroll
    for (int k = 0; k < BK; k++) {
        float a[8], b[8];
        *(float4*)&a[0] = *(const float4*)&As[k][ty * 8];
        *(float4*)&a[4] = *(const float4*)&As[k][ty * 8 + 4];
        *(float4*)&b[0] = *(const float4*)&Bs[k][tx * 8];
        *(float4*)&b[4] = *(const float4*)&Bs[k][tx * 8 + 4];
#pragma unroll
        for (int i = 0; i < 8; i++)
#pragma unroll
            for (int j = 0; j < 8; j++)
                acc[i][j] += a[i] * b[j];
    }
}

// ---------------- K0: conv weight relayout ----------------
// Wc[e][t*256+c] = conv_w[e][c][t]   (conv_w is (512,256,5) row-major)
__global__ void k_prep_w(const float* __restrict__ w, float* __restrict__ wc) {
    int i = blockIdx.x * 256 + threadIdx.x;
    if (i < DIM * KIN) {
        int e = i / KIN;
        int r = i - e * KIN;
        int t = r / TOKD;
        int c = r - t * TOKD;
        wc[i] = w[e * KIN + c * 5 + t];
    }
}

// ---------------- K1: C = alpha * A(MxK) @ B(NxK)^T + bias[n] ----------------
// batched via blockIdx.z with element strides sA,sB,sC (0 for shared operands)
__global__ __launch_bounds__(256) void k_gemm_abt(
    const float* __restrict__ A, const float* __restrict__ Bm, float* __restrict__ C,
    int M, int N, int K, int lda, int ldb, int ldc,
    long long sA, long long sB, long long sC,
    float alpha, const float* __restrict__ bias)
{
    __shared__ float As[BK][BM];
    __shared__ float Bs[BK][BN];
    long long z = blockIdx.z;
    A  += z * sA;
    Bm += z * sB;
    C  += z * sC;
    const int m0 = blockIdx.y * BM, n0 = blockIdx.x * BN;
    const int tid = threadIdx.x;
    const int arow = tid >> 1, acol = (tid & 1) * 4;   // A tile 128x8 (one float4/thread)
    const int tx = tid & 15, ty = tid >> 4;

    float acc[8][8];
#pragma unroll
    for (int i = 0; i < 8; i++)
#pragma unroll
        for (int j = 0; j < 8; j++) acc[i][j] = 0.f;

    const float* Aptr = A  + (long long)(m0 + arow) * lda + acol;
    const float* Bptr = Bm + (long long)(n0 + arow) * ldb + acol;  // B^T load: same pattern

    for (int k0 = 0; k0 < K; k0 += BK) {
        float4 av = *(const float4*)(Aptr + k0);
        As[acol + 0][arow] = av.x; As[acol + 1][arow] = av.y;
        As[acol + 2][arow] = av.z; As[acol + 3][arow] = av.w;
        float4 bv = *(const float4*)(Bptr + k0);
        Bs[acol + 0][arow] = bv.x; Bs[acol + 1][arow] = bv.y;
        Bs[acol + 2][arow] = bv.z; Bs[acol + 3][arow] = bv.w;
        __syncthreads();
        mma_step(As, Bs, acc, ty, tx);
        __syncthreads();
    }

#pragma unroll
    for (int i = 0; i < 8; i++) {
        int r = m0 + ty * 8 + i;
#pragma unroll
        for (int j = 0; j < 8; j += 4) {
            int c = n0 + tx * 8 + j;
            float4 o;
            o.x = alpha * acc[i][j + 0];
            o.y = alpha * acc[i][j + 1];
            o.z = alpha * acc[i][j + 2];
            o.w = alpha * acc[i][j + 3];
            if (bias) {
                float4 bb = *(const float4*)(bias + c);
                o.x += bb.x; o.y += bb.y; o.z += bb.z; o.w += bb.w;
            }
            *(float4*)(C + (long long)r * ldc + c) = o;
        }
    }
}

// ---------------- K2: row-softmax stats (over s, per (b,l) row) ----------------
__global__ void k_row_stats(const float* __restrict__ A,
                            float* __restrict__ rmax, float* __restrict__ rinv) {
    __shared__ float red[256];
    long long r = blockIdx.x;                 // 0 .. 8*1024-1
    const float* row = A + r * SSEQ;
    int tid = threadIdx.x;
    float m = -1e30f;
    for (int c = tid; c < SSEQ; c += 256) m = fmaxf(m, row[c]);
    red[tid] = m; __syncthreads();
    for (int s = 128; s > 0; s >>= 1) {
        if (tid < s) red[tid] = fmaxf(red[tid], red[tid + s]);
        __syncthreads();
    }
    m = red[0];
    __syncthreads();
    float sum = 0.f;
    for (int c = tid; c < SSEQ; c += 256) sum += expf(row[c] - m);
    red[tid] = sum; __syncthreads();
    for (int s = 128; s > 0; s >>= 1) {
        if (tid < s) red[tid] += red[tid + s];
        __syncthreads();
    }
    if (tid == 0) { rmax[r] = m; rinv[r] = 1.f / red[0]; }
}

// ---------------- K3: column-softmax stats (over l, per (b,s) column) ----------------
// online max/sum single pass; coalesced across s
__global__ void k_col_stats(const float* __restrict__ A,
                            float* __restrict__ cmax, float* __restrict__ cinv) {
    int b = blockIdx.y;
    int s = blockIdx.x * 256 + threadIdx.x;
    const float* Ab = A + (long long)b * LSEQ * SSEQ;
    float m = -1e30f, sum = 0.f;
    for (int l = 0; l < LSEQ; l++) {
        float v = Ab[(long long)l * SSEQ + s];
        if (v > m) { sum = sum * expf(m - v) + 1.f; m = v; }
        else       { sum += expf(v - m); }
    }
    cmax[b * SSEQ + s] = m;
    cinv[b * SSEQ + s] = 1.f / sum;
}

// ---------------- K4: delta_lat = softmax_row(A) @ Vtok ; += latents ; dual-store ----------------
// per batch: M=1024 (l), N=512 (e), K=2048 (s)
__global__ __launch_bounds__(256) void k_attn_row(
    const float* __restrict__ Amat, const float* __restrict__ V,
    const float* __restrict__ rmax, const float* __restrict__ rinv,
    const float* __restrict__ addend,
    float* __restrict__ out1, float* __restrict__ out2)
{
    __shared__ float As[BK][BM];
    __shared__ float Bs[BK][BN];
    long long z = blockIdx.z;
    Amat   += z * (long long)LSEQ * SSEQ;
    V      += z * (long long)SSEQ * DIM;
    rmax   += z * LSEQ;
    rinv   += z * LSEQ;
    addend += z * (long long)LSEQ * DIM;
    out1   += z * (long long)LSEQ * DIM;
    out2   += z * (long long)(LSEQ + SSEQ) * DIM;   // concat block stride

    const int m0 = blockIdx.y * BM, n0 = blockIdx.x * BN;
    const int tid = threadIdx.x;
    const int arow = tid >> 1, acol = (tid & 1) * 4;     // A: 128 x 8
    const int bkr = tid >> 5, bnc = (tid & 31) * 4;      // B (KxN): 8 x 128
    const int tx = tid & 15, ty = tid >> 4;

    const float rm = rmax[m0 + arow];
    const float ri = rinv[m0 + arow];

    float acc[8][8];
#pragma unroll
    for (int i = 0; i < 8; i++)
#pragma unroll
        for (int j = 0; j < 8; j++) acc[i][j] = 0.f;

    for (int k0 = 0; k0 < SSEQ; k0 += BK) {
        float4 av = *(const float4*)(Amat + (long long)(m0 + arow) * SSEQ + k0 + acol);
        As[acol + 0][arow] = expf(av.x - rm) * ri;
        As[acol + 1][arow] = expf(av.y - rm) * ri;
        As[acol + 2][arow] = expf(av.z - rm) * ri;
        As[acol + 3][arow] = expf(av.w - rm) * ri;
        float4 bv = *(const float4*)(V + (long long)(k0 + bkr) * DIM + n0 + bnc);
        *(float4*)&Bs[bkr][bnc] = bv;
        __syncthreads();
        mma_step(As, Bs, acc, ty, tx);
        __syncthreads();
    }

#pragma unroll
    for (int i = 0; i < 8; i++) {
        int r = m0 + ty * 8 + i;
#pragma unroll
        for (int j = 0; j < 8; j += 4) {
            int c = n0 + tx * 8 + j;
            float4 ad = *(const float4*)(addend + (long long)r * DIM + c);
            float4 o;
            o.x = acc[i][j + 0] + ad.x;
            o.y = acc[i][j + 1] + ad.y;
            o.z = acc[i][j + 2] + ad.z;
            o.w = acc[i][j + 3] + ad.w;
            *(float4*)(out1 + (long long)r * DIM + c) = o;
            *(float4*)(out2 + (long long)r * DIM + c) = o;
        }
    }
}

// ---------------- K5: delta_tok = softmax_col(A)^T @ Vlat ; += tok ; dual-store ----------------
// per batch: M=2048 (s), N=512 (e), K=1024 (l); A accessed as A[l][s] (coalesced in s)
__global__ __launch_bounds__(256) void k_attn_col(
    const float* __restrict__ Amat, const float* __restrict__ V,
    const float* __restrict__ cmax, const float* __restrict__ cinv,
    const float* __restrict__ addend,
    float* __restrict__ out1, float* __restrict__ out2)
{
    __shared__ float As[BK][BM];
    __shared__ float Bs[BK][BN];
    long long z = blockIdx.z;
    Amat   += z * (long long)LSEQ * SSEQ;
    V      += z * (long long)LSEQ * DIM;
    cmax   += z * SSEQ;
    cinv   += z * SSEQ;
    addend += z * (long long)SSEQ * DIM;
    out1   += z * (long long)SSEQ * DIM;
    out2   += z * (long long)(LSEQ + SSEQ) * DIM;

    const int m0 = blockIdx.y * BM, n0 = blockIdx.x * BN;
    const int tid = threadIdx.x;
    const int alr = tid >> 5, asc = (tid & 31) * 4;      // A tile: 8 (l) x 128 (s)
    const int bkr = tid >> 5, bnc = (tid & 31) * 4;      // B (KxN): 8 x 128
    const int tx = tid & 15, ty = tid >> 4;

    const float4 cm = *(const float4*)(cmax + m0 + asc);
    const float4 ci = *(const float4*)(cinv + m0 + asc);

    float acc[8][8];
#pragma unroll
    for (int i = 0; i < 8; i++)
#pragma unroll
        for (int j = 0; j < 8; j++) acc[i][j] = 0.f;

    for (int k0 = 0; k0 < LSEQ; k0 += BK) {
        float4 av = *(const float4*)(Amat + (long long)(k0 + alr) * SSEQ + m0 + asc);
        As[alr][asc + 0] = expf(av.x - cm.x) * ci.x;
        As[alr][asc + 1] = expf(av.y - cm.y) * ci.y;
        As[alr][asc + 2] = expf(av.z - cm.z) * ci.z;
        As[alr][asc + 3] = expf(av.w - cm.w) * ci.w;
        float4 bv = *(const float4*)(V + (long long)(k0 + bkr) * DIM + n0 + bnc);
        *(float4*)&Bs[bkr][bnc] = bv;
        __syncthreads();
        mma_step(As, Bs, acc, ty, tx);
        __syncthreads();
    }

#pragma unroll
    for (int i = 0; i < 8; i++) {
        int r = m0 + ty * 8 + i;
#pragma unroll
        for (int j = 0; j < 8; j += 4) {
            int c = n0 + tx * 8 + j;
            float4 ad = *(const float4*)(addend + (long long)r * DIM + c);
            float4 o;
            o.x = acc[i][j + 0] + ad.x;
            o.y = acc[i][j + 1] + ad.y;
            o.z = acc[i][j + 2] + ad.z;
            o.w = acc[i][j + 3] + ad.w;
            *(float4*)(out1 + (long long)r * DIM + c) = o;
            *(float4*)(out2 + (long long)r * DIM + c) = o;
        }
    }
}

// ---------------- launch ----------------
extern "C" void kernel_launch(void* const* d_in, const int* in_sizes, int n_in,
                              void* d_out, int out_size) {
    const float* latents = (const float*)d_in[0];
    const float* tokens  = (const float*)d_in[1];
    const float* W_lat   = (const float*)d_in[2];
    const float* W_tok   = (const float*)d_in[3];
    const float* W_vlat  = (const float*)d_in[4];
    const float* W_vtok  = (const float*)d_in[5];
    const float* conv_w  = (const float*)d_in[6];
    const float* conv_b  = (const float*)d_in[7];
    float* out = (float*)d_out;

    float *wc, *tok, *rlat, *rtok, *vlat, *vtok, *smat, *rmax, *rinv, *cmax, *cinv;
    cudaGetSymbolAddress((void**)&wc,   g_Wc);
    cudaGetSymbolAddress((void**)&tok,  g_tok);
    cudaGetSymbolAddress((void**)&rlat, g_Rlat);
    cudaGetSymbolAddress((void**)&rtok, g_Rtok);
    cudaGetSymbolAddress((void**)&vlat, g_Vlat);
    cudaGetSymbolAddress((void**)&vtok, g_Vtok);
    cudaGetSymbolAddress((void**)&smat, g_S);
    cudaGetSymbolAddress((void**)&rmax, g_rmax);
    cudaGetSymbolAddress((void**)&rinv, g_rinv);
    cudaGetSymbolAddress((void**)&cmax, g_cmax);
    cudaGetSymbolAddress((void**)&cinv, g_cinv);

    const long long UL = (long long)NB * LSEQ * DIM;     // 4,194,304
    const long long UT = (long long)NB * SSEQ * DIM;     // 8,388,608
    const long long CONCAT = UL + UT;                    // 12,582,912

    // conv weight relayout
    k_prep_w<<<(DIM * KIN + 255) / 256, 256>>>(conv_w, wc);

    // conv as GEMM: tok(16384x512) = tokens(16384x1280) @ Wc^T + bias
    k_gemm_abt<<<dim3(DIM / BN, (NB * SSEQ) / BM, 1), 256>>>(
        tokens, wc, tok, NB * SSEQ, DIM, KIN, KIN, KIN, DIM, 0, 0, 0, 1.f, conv_b);

    // projections (no bias)
    k_gemm_abt<<<dim3(DIM / BN, (NB * LSEQ) / BM, 1), 256>>>(
        latents, W_lat, rlat, NB * LSEQ, DIM, DIM, DIM, DIM, DIM, 0, 0, 0, 1.f, nullptr);
    k_gemm_abt<<<dim3(DIM / BN, (NB * LSEQ) / BM, 1), 256>>>(
        latents, W_vlat, vlat, NB * LSEQ, DIM, DIM, DIM, DIM, DIM, 0, 0, 0, 1.f, nullptr);
    k_gemm_abt<<<dim3(DIM / BN, (NB * SSEQ) / BM, 1), 256>>>(
        tok, W_tok, rtok, NB * SSEQ, DIM, DIM, DIM, DIM, DIM, 0, 0, 0, 1.f, nullptr);
    k_gemm_abt<<<dim3(DIM / BN, (NB * SSEQ) / BM, 1), 256>>>(
        tok, W_vtok, vtok, NB * SSEQ, DIM, DIM, DIM, DIM, DIM, 0, 0, 0, 1.f, nullptr);

    // scores: per batch A = Rlat @ Rtok^T * 1/sqrt(512)
    const float scale = 0.044194173824159216f;  // 1/sqrt(512)
    k_gemm_abt<<<dim3(SSEQ / BN, LSEQ / BM, NB), 256>>>(
        rlat, rtok, smat, LSEQ, SSEQ, DIM, DIM, DIM, SSEQ,
        (long long)LSEQ * DIM, (long long)SSEQ * DIM, (long long)LSEQ * SSEQ,
        scale, nullptr);

    // softmax stats
    k_row_stats<<<NB * LSEQ, 256>>>(smat, rmax, rinv);
    k_col_stats<<<dim3(SSEQ / 256, NB), 256>>>(smat, cmax, cinv);

    // delta_lat + residual, writes updated_latents region + concat region
    k_attn_row<<<dim3(DIM / BN, LSEQ / BM, NB), 256>>>(
        smat, vtok, rmax, rinv, latents, out, out + CONCAT);

    // delta_tok + residual, writes updated_tokens region + concat region (offset by L rows)
    k_attn_col<<<dim3(DIM / BN, SSEQ / BM, NB), 256>>>(
        smat, vlat, cmax, cinv, tok, out + UL, out + CONCAT + (long long)LSEQ * DIM);
}

// round 2
// speedup vs baseline: 2.6432x; 2.6432x over previous
#include <cuda_runtime.h>
#include <math.h>
#include <stdint.h>

// ---------------- problem constants ----------------
#define NB   8
#define LSEQ 1024
#define SSEQ 2048
#define DIM  512
#define TOKD 256
#define KIN  1280

// ---------------- scratch ----------------
__device__ __align__(256) float g_Wc  [DIM * KIN];
__device__ __align__(256) float g_tok [NB * SSEQ * DIM];
__device__ __align__(256) float g_Rlat[NB * LSEQ * DIM];
__device__ __align__(256) float g_Rtok[NB * SSEQ * DIM];
__device__ __align__(256) float g_Vlat[NB * LSEQ * DIM];
__device__ __align__(256) float g_Vtok[NB * SSEQ * DIM];
__device__ __align__(256) float g_S   [NB * LSEQ * SSEQ];
__device__ __align__(256) float g_rmax[NB * LSEQ];
__device__ __align__(256) float g_rinv[NB * LSEQ];
__device__ __align__(256) float g_cmax[NB * SSEQ];
__device__ __align__(256) float g_cinv[NB * SSEQ];

// ---------------- tensor-core GEMM config ----------------
#define BM 128
#define BN 128
#define BK 16
#define P0 20     // smem stride for [row][k] tiles (conflict-free frag loads)
#define P1 136    // smem stride for [k][col] tiles

__device__ __forceinline__ float f2tf(float x) {
    uint32_t r;
    asm("cvt.rna.tf32.f32 %0, %1;" : "=r"(r) : "f"(x));
    return __uint_as_float(r);
}

__device__ __forceinline__ void mma_tf32(float c[4], const uint32_t a[4], const uint32_t b[2]) {
    asm volatile(
        "mma.sync.aligned.m16n8k8.row.col.f32.tf32.tf32.f32 "
        "{%0,%1,%2,%3}, {%4,%5,%6,%7}, {%8,%9}, {%0,%1,%2,%3};"
        : "+f"(c[0]), "+f"(c[1]), "+f"(c[2]), "+f"(c[3])
        : "r"(a[0]), "r"(a[1]), "r"(a[2]), "r"(a[3]), "r"(b[0]), "r"(b[1]));
}

// ---------------- generic TF32 tensor-core GEMM ----------------
// C(M,N) = op(A) @ op(B), with:
//   ALAY=0: A is (M,K) row-major (k contiguous)      ALAY=1: A is (K,M) row-major (m contiguous)
//   BLAY=0: B is (N,K) row-major (k contiguous)      BLAY=1: B is (K,N) row-major (n contiguous)
//   TRANSA=0: none;  1: row-softmax exp((x-smax[m])) * sinv[m] (ALAY=0)
//             2: col-softmax, stats indexed by m (ALAY=1)
//   EPI=0: C = alpha*acc + bias[n]        EPI=1: v = acc + addend; store C and C2
template<int ALAY, int BLAY, int TRANSA, int EPI>
__global__ __launch_bounds__(256, 2) void k_gemm_tc(
    const float* __restrict__ A, const float* __restrict__ B,
    float* __restrict__ C, float* __restrict__ C2,
    int K, int lda, int ldb, int ldc,
    long long sA, long long sB, long long sC, long long sC2,
    float alpha, const float* __restrict__ bias,
    const float* __restrict__ smax, const float* __restrict__ sinv, int sstat,
    const float* __restrict__ addend, long long sAdd)
{
    constexpr int ASZ = ALAY ? BK * P1 : BM * P0;
    constexpr int BSZ = BLAY ? BK * P1 : BN * P0;
    __shared__ float As[2][ASZ];
    __shared__ float Bs[2][BSZ];

    const long long z = blockIdx.z;
    A += z * sA;
    B += z * sB;
    C += z * sC;
    if (EPI == 1) { C2 += z * sC2; addend += z * sAdd; }

    const int m0 = blockIdx.y * BM, n0 = blockIdx.x * BN;
    const int tid = threadIdx.x;
    const int wid = tid >> 5, lane = tid & 31;
    const int grp = lane >> 2, tig = lane & 3;
    const int wm = (wid >> 2) * 64, wn = (wid & 3) * 32;

    // loader indices
    const int l0row = tid >> 1, l0kq = (tid & 1);    // layout0: row, k-quad
    const int l1k0 = tid >> 5, l1c = (tid & 31) * 4; // layout1: k row, col

    // softmax stats (indexed by output row m in both cases)
    float tr_m = 0.f, tr_i = 1.f;
    float4 tc_m = {0, 0, 0, 0}, tc_i = {1, 1, 1, 1};
    if (TRANSA == 1) {
        tr_m = smax[z * sstat + m0 + l0row];
        tr_i = sinv[z * sstat + m0 + l0row];
    }
    if (TRANSA == 2) {
        tc_m = *(const float4*)(smax + z * sstat + m0 + l1c);
        tc_i = *(const float4*)(sinv + z * sstat + m0 + l1c);
    }

    float acc[4][4][4];
#pragma unroll
    for (int i = 0; i < 4; i++)
#pragma unroll
        for (int j = 0; j < 4; j++)
#pragma unroll
            for (int r = 0; r < 4; r++) acc[i][j][r] = 0.f;

    float4 ra0, ra1, rb0, rb1;

    auto ldA = [&](int t) {
        const int k0 = t * BK;
        if (ALAY == 0) {
            const float* p = A + (long long)(m0 + l0row) * lda + k0 + l0kq * 4;
            ra0 = *(const float4*)p;
            ra1 = *(const float4*)(p + 8);
        } else {
            const float* p = A + (long long)(k0 + l1k0) * lda + m0 + l1c;
            ra0 = *(const float4*)p;
            ra1 = *(const float4*)(p + 8LL * lda);
        }
    };
    auto ldB = [&](int t) {
        const int k0 = t * BK;
        if (BLAY == 0) {
            const float* p = B + (long long)(n0 + l0row) * ldb + k0 + l0kq * 4;
            rb0 = *(const float4*)p;
            rb1 = *(const float4*)(p + 8);
        } else {
            const float* p = B + (long long)(k0 + l1k0) * ldb + n0 + l1c;
            rb0 = *(const float4*)p;
            rb1 = *(const float4*)(p + 8LL * ldb);
        }
    };

    auto xfA = [&](float4 v) -> float4 {
        if (TRANSA == 1) {
            v.x = __expf(v.x - tr_m) * tr_i;
            v.y = __expf(v.y - tr_m) * tr_i;
            v.z = __expf(v.z - tr_m) * tr_i;
            v.w = __expf(v.w - tr_m) * tr_i;
        } else if (TRANSA == 2) {
            v.x = __expf(v.x - tc_m.x) * tc_i.x;
            v.y = __expf(v.y - tc_m.y) * tc_i.y;
            v.z = __expf(v.z - tc_m.z) * tc_i.z;
            v.w = __expf(v.w - tc_m.w) * tc_i.w;
        }
        return v;
    };
    auto tfq = [&](float4 v) -> float4 {
        float4 o;
        o.x = f2tf(v.x); o.y = f2tf(v.y); o.z = f2tf(v.z); o.w = f2tf(v.w);
        return o;
    };

    auto stsA = [&](int buf) {
        float4 v0 = tfq(xfA(ra0)), v1 = tfq(xfA(ra1));
        if (ALAY == 0) {
            float* p = &As[buf][l0row * P0 + l0kq * 4];
            *(float4*)p = v0;
            *(float4*)(p + 8) = v1;
        } else {
            *(float4*)&As[buf][l1k0 * P1 + l1c] = v0;
            *(float4*)&As[buf][(l1k0 + 8) * P1 + l1c] = v1;
        }
    };
    auto stsB = [&](int buf) {
        float4 v0 = tfq(rb0), v1 = tfq(rb1);
        if (BLAY == 0) {
            float* p = &Bs[buf][l0row * P0 + l0kq * 4];
            *(float4*)p = v0;
            *(float4*)(p + 8) = v1;
        } else {
            *(float4*)&Bs[buf][l1k0 * P1 + l1c] = v0;
            *(float4*)&Bs[buf][(l1k0 + 8) * P1 + l1c] = v1;
        }
    };

    auto compute = [&](int buf) {
        const uint32_t* Au = (const uint32_t*)As[buf];
        const uint32_t* Bu = (const uint32_t*)Bs[buf];
#pragma unroll
        for (int ks = 0; ks < BK; ks += 8) {
            uint32_t af[4][4], bf[4][2];
#pragma unroll
            for (int mi = 0; mi < 4; mi++) {
                const int mr = wm + mi * 16 + grp;
                if (ALAY == 0) {
                    const uint32_t* p = Au + mr * P0 + ks + tig;
                    af[mi][0] = p[0];
                    af[mi][1] = p[8 * P0];
                    af[mi][2] = p[4];
                    af[mi][3] = p[8 * P0 + 4];
                } else {
                    const uint32_t* p = Au + (ks + tig) * P1 + mr;
                    af[mi][0] = p[0];
                    af[mi][1] = p[8];
                    af[mi][2] = p[4 * P1];
                    af[mi][3] = p[4 * P1 + 8];
                }
            }
#pragma unroll
            for (int ni = 0; ni < 4; ni++) {
                const int nc = wn + ni * 8 + grp;
                if (BLAY == 0) {
                    const uint32_t* p = Bu + nc * P0 + ks + tig;
                    bf[ni][0] = p[0];
                    bf[ni][1] = p[4];
                } else {
                    const uint32_t* p = Bu + (ks + tig) * P1 + nc;
                    bf[ni][0] = p[0];
                    bf[ni][1] = p[4 * P1];
                }
            }
#pragma unroll
            for (int mi = 0; mi < 4; mi++)
#pragma unroll
                for (int ni = 0; ni < 4; ni++)
                    mma_tf32(acc[mi][ni], af[mi], bf[ni]);
        }
    };

    const int tiles = K / BK;
    ldA(0); ldB(0);
    stsA(0); stsB(0);
    __syncthreads();
    for (int t = 0; t < tiles; t++) {
        const int cur = t & 1;
        if (t + 1 < tiles) { ldA(t + 1); ldB(t + 1); }
        compute(cur);
        if (t + 1 < tiles) {
            stsA(cur ^ 1); stsB(cur ^ 1);
            __syncthreads();
        }
    }

    // epilogue
#pragma unroll
    for (int mi = 0; mi < 4; mi++) {
        const int r = m0 + wm + mi * 16 + grp;
#pragma unroll
        for (int ni = 0; ni < 4; ni++) {
            const int c = n0 + wn + ni * 8 + tig * 2;
            float2 v0 = {acc[mi][ni][0], acc[mi][ni][1]};
            float2 v1 = {acc[mi][ni][2], acc[mi][ni][3]};
            if (EPI == 0) {
                float bx = 0.f, by = 0.f;
                if (bias) { bx = bias[c]; by = bias[c + 1]; }
                v0.x = alpha * v0.x + bx; v0.y = alpha * v0.y + by;
                v1.x = alpha * v1.x + bx; v1.y = alpha * v1.y + by;
                *(float2*)(C + (long long)r * ldc + c) = v0;
                *(float2*)(C + (long long)(r + 8) * ldc + c) = v1;
            } else {
                float2 a0 = *(const float2*)(addend + (long long)r * ldc + c);
                float2 a1 = *(const float2*)(addend + (long long)(r + 8) * ldc + c);
                v0.x += a0.x; v0.y += a0.y;
                v1.x += a1.x; v1.y += a1.y;
                *(float2*)(C  + (long long)r * ldc + c) = v0;
                *(float2*)(C  + (long long)(r + 8) * ldc + c) = v1;
                *(float2*)(C2 + (long long)r * ldc + c) = v0;
                *(float2*)(C2 + (long long)(r + 8) * ldc + c) = v1;
            }
        }
    }
}

// ---------------- conv weight relayout ----------------
__global__ void k_prep_w(const float* __restrict__ w, float* __restrict__ wc) {
    int i = blockIdx.x * 256 + threadIdx.x;
    if (i < DIM * KIN) {
        int e = i / KIN;
        int r = i - e * KIN;
        int t = r / TOKD;
        int c = r - t * TOKD;
        wc[i] = w[e * KIN + c * 5 + t];
    }
}

// ---------------- softmax stats ----------------
__global__ void k_row_stats(const float* __restrict__ A,
                            float* __restrict__ rmax, float* __restrict__ rinv) {
    __shared__ float red[256];
    long long r = blockIdx.x;
    const float* row = A + r * SSEQ;
    int tid = threadIdx.x;
    float m = -1e30f;
    for (int c = tid; c < SSEQ; c += 256) m = fmaxf(m, row[c]);
    red[tid] = m; __syncthreads();
    for (int s = 128; s > 0; s >>= 1) {
        if (tid < s) red[tid] = fmaxf(red[tid], red[tid + s]);
        __syncthreads();
    }
    m = red[0];
    __syncthreads();
    float sum = 0.f;
    for (int c = tid; c < SSEQ; c += 256) sum += __expf(row[c] - m);
    red[tid] = sum; __syncthreads();
    for (int s = 128; s > 0; s >>= 1) {
        if (tid < s) red[tid] += red[tid + s];
        __syncthreads();
    }
    if (tid == 0) { rmax[r] = m; rinv[r] = 1.f / red[0]; }
}

__global__ void k_col_stats(const float* __restrict__ A,
                            float* __restrict__ cmax, float* __restrict__ cinv) {
    int b = blockIdx.y;
    int s = blockIdx.x * 256 + threadIdx.x;
    const float* Ab = A + (long long)b * LSEQ * SSEQ;
    float m = -1e30f, sum = 0.f;
    for (int l = 0; l < LSEQ; l++) {
        float v = Ab[(long long)l * SSEQ + s];
        if (v > m) { sum = sum * __expf(m - v) + 1.f; m = v; }
        else       { sum += __expf(v - m); }
    }
    cmax[b * SSEQ + s] = m;
    cinv[b * SSEQ + s] = 1.f / sum;
}

// ---------------- launch ----------------
extern "C" void kernel_launch(void* const* d_in, const int* in_sizes, int n_in,
                              void* d_out, int out_size) {
    const float* latents = (const float*)d_in[0];
    const float* tokens  = (const float*)d_in[1];
    const float* W_lat   = (const float*)d_in[2];
    const float* W_tok   = (const float*)d_in[3];
    const float* W_vlat  = (const float*)d_in[4];
    const float* W_vtok  = (const float*)d_in[5];
    const float* conv_w  = (const float*)d_in[6];
    const float* conv_b  = (const float*)d_in[7];
    float* out = (float*)d_out;

    float *wc, *tok, *rlat, *rtok, *vlat, *vtok, *smat, *rmax, *rinv, *cmax, *cinv;
    cudaGetSymbolAddress((void**)&wc,   g_Wc);
    cudaGetSymbolAddress((void**)&tok,  g_tok);
    cudaGetSymbolAddress((void**)&rlat, g_Rlat);
    cudaGetSymbolAddress((void**)&rtok, g_Rtok);
    cudaGetSymbolAddress((void**)&vlat, g_Vlat);
    cudaGetSymbolAddress((void**)&vtok, g_Vtok);
    cudaGetSymbolAddress((void**)&smat, g_S);
    cudaGetSymbolAddress((void**)&rmax, g_rmax);
    cudaGetSymbolAddress((void**)&rinv, g_rinv);
    cudaGetSymbolAddress((void**)&cmax, g_cmax);
    cudaGetSymbolAddress((void**)&cinv, g_cinv);

    const long long UL = (long long)NB * LSEQ * DIM;
    const long long UT = (long long)NB * SSEQ * DIM;
    const long long CONCAT = UL + UT;

    k_prep_w<<<(DIM * KIN + 255) / 256, 256>>>(conv_w, wc);

    // conv as GEMM: tok = tokens(16384x1280) @ Wc^T + bias
    k_gemm_tc<0, 0, 0, 0><<<dim3(DIM / BN, (NB * SSEQ) / BM, 1), 256>>>(
        tokens, wc, tok, nullptr, KIN, KIN, KIN, DIM, 0, 0, 0, 0,
        1.f, conv_b, nullptr, nullptr, 0, nullptr, 0);

    // projections
    k_gemm_tc<0, 0, 0, 0><<<dim3(DIM / BN, (NB * LSEQ) / BM, 1), 256>>>(
        latents, W_lat, rlat, nullptr, DIM, DIM, DIM, DIM, 0, 0, 0, 0,
        1.f, nullptr, nullptr, nullptr, 0, nullptr, 0);
    k_gemm_tc<0, 0, 0, 0><<<dim3(DIM / BN, (NB * LSEQ) / BM, 1), 256>>>(
        latents, W_vlat, vlat, nullptr, DIM, DIM, DIM, DIM, 0, 0, 0, 0,
        1.f, nullptr, nullptr, nullptr, 0, nullptr, 0);
    k_gemm_tc<0, 0, 0, 0><<<dim3(DIM / BN, (NB * SSEQ) / BM, 1), 256>>>(
        tok, W_tok, rtok, nullptr, DIM, DIM, DIM, DIM, 0, 0, 0, 0,
        1.f, nullptr, nullptr, nullptr, 0, nullptr, 0);
    k_gemm_tc<0, 0, 0, 0><<<dim3(DIM / BN, (NB * SSEQ) / BM, 1), 256>>>(
        tok, W_vtok, vtok, nullptr, DIM, DIM, DIM, DIM, 0, 0, 0, 0,
        1.f, nullptr, nullptr, nullptr, 0, nullptr, 0);

    // scores: A = Rlat @ Rtok^T / sqrt(512)
    const float scale = 0.044194173824159216f;
    k_gemm_tc<0, 0, 0, 0><<<dim3(SSEQ / BN, LSEQ / BM, NB), 256>>>(
        rlat, rtok, smat, nullptr, DIM, DIM, DIM, SSEQ,
        (long long)LSEQ * DIM, (long long)SSEQ * DIM, (long long)LSEQ * SSEQ, 0,
        scale, nullptr, nullptr, nullptr, 0, nullptr, 0);

    k_row_stats<<<NB * LSEQ, 256>>>(smat, rmax, rinv);
    k_col_stats<<<dim3(SSEQ / 256, NB), 256>>>(smat, cmax, cinv);

    // delta_lat = softmax_row(A) @ Vtok + latents  -> out[0:UL] and concat
    k_gemm_tc<0, 1, 1, 1><<<dim3(DIM / BN, LSEQ / BM, NB), 256>>>(
        smat, vtok, out, out + CONCAT, SSEQ, SSEQ, DIM, DIM,
        (long long)LSEQ * SSEQ, (long long)SSEQ * DIM,
        (long long)LSEQ * DIM, (long long)(LSEQ + SSEQ) * DIM,
        1.f, nullptr, rmax, rinv, LSEQ, latents, (long long)LSEQ * DIM);

    // delta_tok = softmax_col(A)^T @ Vlat + tok -> out[UL:UL+UT] and concat(+L rows)
    k_gemm_tc<1, 1, 2, 1><<<dim3(DIM / BN, SSEQ / BM, NB), 256>>>(
        smat, vlat, out + UL, out + CONCAT + (long long)LSEQ * DIM, LSEQ, SSEQ, DIM, DIM,
        (long long)LSEQ * SSEQ, (long long)LSEQ * DIM,
        (long long)SSEQ * DIM, (long long)(LSEQ + SSEQ) * DIM,
        1.f, nullptr, cmax, cinv, SSEQ, tok, (long long)SSEQ * DIM);
}

// round 3
// speedup vs baseline: 3.2253x; 1.2202x over previous
#include <cuda_runtime.h>
#include <math.h>
#include <stdint.h>

// ---------------- problem constants ----------------
#define NB   8
#define LSEQ 1024
#define SSEQ 2048
#define DIM  512
#define TOKD 256
#define KIN  1280

// ---------------- scratch ----------------
__device__ __align__(256) float g_Wc  [DIM * KIN];
__device__ __align__(256) float g_tok [NB * SSEQ * DIM];
__device__ __align__(256) float g_Rlat[NB * LSEQ * DIM];
__device__ __align__(256) float g_Rtok[NB * SSEQ * DIM];
__device__ __align__(256) float g_Vlat[NB * LSEQ * DIM];
__device__ __align__(256) float g_Vtok[NB * SSEQ * DIM];
__device__ __align__(256) float g_S   [NB * LSEQ * SSEQ];   // scores, then Prow in place
__device__ __align__(256) float g_PcT [NB * SSEQ * LSEQ];   // col-softmax, transposed (S,L)
__device__ __align__(256) float g_rmax[NB * LSEQ];
__device__ __align__(256) float g_rinv[NB * LSEQ];
__device__ __align__(256) float g_cmax[NB * SSEQ];
__device__ __align__(256) float g_cinv[NB * SSEQ];

// ---------------- GEMM config ----------------
#define BM 128
#define BN 128
#define BK 16
#define P0 20     // [row][k] smem stride
#define P1 132    // [k][col] smem stride

__device__ __forceinline__ uint32_t tf32r(float x) {
    uint32_t r;
    asm("cvt.rna.tf32.f32 %0, %1;" : "=r"(r) : "f"(x));
    return r;
}

__device__ __forceinline__ void mma_tf32(float c[4], const uint32_t a[4], const uint32_t b[2]) {
    asm volatile(
        "mma.sync.aligned.m16n8k8.row.col.f32.tf32.tf32.f32 "
        "{%0,%1,%2,%3}, {%4,%5,%6,%7}, {%8,%9}, {%0,%1,%2,%3};"
        : "+f"(c[0]), "+f"(c[1]), "+f"(c[2]), "+f"(c[3])
        : "r"(a[0]), "r"(a[1]), "r"(a[2]), "r"(a[3]), "r"(b[0]), "r"(b[1]));
}

__device__ __forceinline__ void cpasync16(void* dst, const void* src) {
    uint32_t d = (uint32_t)__cvta_generic_to_shared(dst);
    asm volatile("cp.async.cg.shared.global [%0], [%1], 16;" :: "r"(d), "l"(src));
}

// ---------------- TF32 tensor-core GEMM, cp.async double-buffered ----------------
// C(M,N) = alpha * A(M,K) @ op(B)
//   BLAY=0: B is (N,K) k-contiguous     BLAY=1: B is (K,N) n-contiguous
//   EPI=0:  C = alpha*acc + bias[n]     EPI=1: v = acc + addend; store C and C2
template<int BLAY, int EPI>
__global__ __launch_bounds__(256, 2) void k_gemm_tc(
    const float* __restrict__ A, const float* __restrict__ B,
    float* __restrict__ C, float* __restrict__ C2,
    int K, int lda, int ldb, int ldc,
    long long sA, long long sB, long long sC, long long sC2,
    float alpha, const float* __restrict__ bias,
    const float* __restrict__ addend, long long sAdd)
{
    constexpr int BSZ = BLAY ? BK * P1 : BN * P0;
    __shared__ float As[2][BM * P0];
    __shared__ float Bs[2][BSZ];

    const long long z = blockIdx.z;
    A += z * sA;
    B += z * sB;
    C += z * sC;
    if (EPI == 1) { C2 += z * sC2; addend += z * sAdd; }

    const int m0 = blockIdx.y * BM, n0 = blockIdx.x * BN;
    const int tid = threadIdx.x;
    const int wid = tid >> 5, lane = tid & 31;
    const int grp = lane >> 2, tig = lane & 3;
    const int wm = (wid >> 2) * 64, wn = (wid & 3) * 32;

    float acc[4][4][4];
#pragma unroll
    for (int i = 0; i < 4; i++)
#pragma unroll
        for (int j = 0; j < 4; j++)
#pragma unroll
            for (int r = 0; r < 4; r++) acc[i][j][r] = 0.f;

    auto loadTile = [&](int t, int buf) {
        const int k0 = t * BK;
#pragma unroll
        for (int i = 0; i < 2; i++) {
            int idx = i * 256 + tid;
            int row = idx >> 2, seg = idx & 3;
            cpasync16(&As[buf][row * P0 + seg * 4],
                      A + (long long)(m0 + row) * lda + k0 + seg * 4);
        }
        if (BLAY == 0) {
#pragma unroll
            for (int i = 0; i < 2; i++) {
                int idx = i * 256 + tid;
                int row = idx >> 2, seg = idx & 3;
                cpasync16(&Bs[buf][row * P0 + seg * 4],
                          B + (long long)(n0 + row) * ldb + k0 + seg * 4);
            }
        } else {
#pragma unroll
            for (int i = 0; i < 2; i++) {
                int idx = i * 256 + tid;
                int kr = idx >> 5, seg = idx & 31;
                cpasync16(&Bs[buf][kr * P1 + seg * 4],
                          B + (long long)(k0 + kr) * ldb + n0 + seg * 4);
            }
        }
        asm volatile("cp.async.commit_group;");
    };

    auto compute = [&](int buf) {
        const float* Af = As[buf];
        const float* Bf = Bs[buf];
#pragma unroll
        for (int ks = 0; ks < BK; ks += 8) {
            uint32_t af[4][4], bf[4][2];
#pragma unroll
            for (int mi = 0; mi < 4; mi++) {
                const int mr = wm + mi * 16 + grp;
                const float* p = Af + mr * P0 + ks + tig;
                af[mi][0] = tf32r(p[0]);
                af[mi][1] = tf32r(p[8 * P0]);
                af[mi][2] = tf32r(p[4]);
                af[mi][3] = tf32r(p[8 * P0 + 4]);
            }
#pragma unroll
            for (int ni = 0; ni < 4; ni++) {
                const int nc = wn + ni * 8 + grp;
                if (BLAY == 0) {
                    const float* p = Bf + nc * P0 + ks + tig;
                    bf[ni][0] = tf32r(p[0]);
                    bf[ni][1] = tf32r(p[4]);
                } else {
                    const float* p = Bf + (ks + tig) * P1 + nc;
                    bf[ni][0] = tf32r(p[0]);
                    bf[ni][1] = tf32r(p[4 * P1]);
                }
            }
#pragma unroll
            for (int mi = 0; mi < 4; mi++)
#pragma unroll
                for (int ni = 0; ni < 4; ni++)
                    mma_tf32(acc[mi][ni], af[mi], bf[ni]);
        }
    };

    const int tiles = K / BK;
    loadTile(0, 0);
    for (int t = 0; t < tiles; t++) {
        if (t + 1 < tiles) {
            loadTile(t + 1, (t + 1) & 1);
            asm volatile("cp.async.wait_group 1;");
        } else {
            asm volatile("cp.async.wait_group 0;");
        }
        __syncthreads();
        compute(t & 1);
        __syncthreads();
    }

    // epilogue
#pragma unroll
    for (int mi = 0; mi < 4; mi++) {
        const int r = m0 + wm + mi * 16 + grp;
#pragma unroll
        for (int ni = 0; ni < 4; ni++) {
            const int c = n0 + wn + ni * 8 + tig * 2;
            float2 v0 = {acc[mi][ni][0], acc[mi][ni][1]};
            float2 v1 = {acc[mi][ni][2], acc[mi][ni][3]};
            if (EPI == 0) {
                float bx = 0.f, by = 0.f;
                if (bias) { bx = bias[c]; by = bias[c + 1]; }
                v0.x = alpha * v0.x + bx; v0.y = alpha * v0.y + by;
                v1.x = alpha * v1.x + bx; v1.y = alpha * v1.y + by;
                *(float2*)(C + (long long)r * ldc + c) = v0;
                *(float2*)(C + (long long)(r + 8) * ldc + c) = v1;
            } else {
                float2 a0 = *(const float2*)(addend + (long long)r * ldc + c);
                float2 a1 = *(const float2*)(addend + (long long)(r + 8) * ldc + c);
                v0.x += a0.x; v0.y += a0.y;
                v1.x += a1.x; v1.y += a1.y;
                *(float2*)(C  + (long long)r * ldc + c) = v0;
                *(float2*)(C  + (long long)(r + 8) * ldc + c) = v1;
                *(float2*)(C2 + (long long)r * ldc + c) = v0;
                *(float2*)(C2 + (long long)(r + 8) * ldc + c) = v1;
            }
        }
    }
}

// ---------------- conv weight relayout ----------------
__global__ void k_prep_w(const float* __restrict__ w, float* __restrict__ wc) {
    int i = blockIdx.x * 256 + threadIdx.x;
    if (i < DIM * KIN) {
        int e = i / KIN;
        int r = i - e * KIN;
        int t = r / TOKD;
        int c = r - t * TOKD;
        wc[i] = w[e * KIN + c * 5 + t];
    }
}

// ---------------- softmax stats ----------------
__global__ void k_row_stats(const float* __restrict__ A,
                            float* __restrict__ rmax, float* __restrict__ rinv) {
    __shared__ float red[256];
    long long r = blockIdx.x;
    const float* row = A + r * SSEQ;
    int tid = threadIdx.x;
    float m = -1e30f;
    for (int c = tid; c < SSEQ; c += 256) m = fmaxf(m, row[c]);
    red[tid] = m; __syncthreads();
    for (int s = 128; s > 0; s >>= 1) {
        if (tid < s) red[tid] = fmaxf(red[tid], red[tid + s]);
        __syncthreads();
    }
    m = red[0];
    __syncthreads();
    float sum = 0.f;
    for (int c = tid; c < SSEQ; c += 256) sum += __expf(row[c] - m);
    red[tid] = sum; __syncthreads();
    for (int s = 128; s > 0; s >>= 1) {
        if (tid < s) red[tid] += red[tid + s];
        __syncthreads();
    }
    if (tid == 0) { rmax[r] = m; rinv[r] = 1.f / red[0]; }
}

__global__ void k_col_stats(const float* __restrict__ A,
                            float* __restrict__ cmax, float* __restrict__ cinv) {
    int b = blockIdx.y;
    int s = blockIdx.x * 256 + threadIdx.x;
    const float* Ab = A + (long long)b * LSEQ * SSEQ;
    float m = -1e30f, sum = 0.f;
    for (int l = 0; l < LSEQ; l++) {
        float v = Ab[(long long)l * SSEQ + s];
        if (v > m) { sum = sum * __expf(m - v) + 1.f; m = v; }
        else       { sum += __expf(v - m); }
    }
    cmax[b * SSEQ + s] = m;
    cinv[b * SSEQ + s] = 1.f / sum;
}

// ---------------- apply both softmaxes: Prow in place, PcolT transposed ----------------
__global__ __launch_bounds__(256) void k_softmax_apply(
    float* __restrict__ A, float* __restrict__ PcT,
    const float* __restrict__ rmax, const float* __restrict__ rinv,
    const float* __restrict__ cmax, const float* __restrict__ cinv)
{
    __shared__ float tile[32][33];
    const int b = blockIdx.z;
    const int s0 = blockIdx.x * 32, l0 = blockIdx.y * 32;
    float* Ab = A + (long long)b * LSEQ * SSEQ;
    float* Pb = PcT + (long long)b * SSEQ * LSEQ;
    const int tx = threadIdx.x & 31, ty = threadIdx.x >> 5;  // 32 x 8

    const float cm = cmax[b * SSEQ + s0 + tx];
    const float ci = cinv[b * SSEQ + s0 + tx];
#pragma unroll
    for (int i = 0; i < 4; i++) {
        const int l = l0 + ty + i * 8;
        float v = Ab[(long long)l * SSEQ + s0 + tx];
        Ab[(long long)l * SSEQ + s0 + tx] = __expf(v - rmax[b * LSEQ + l]) * rinv[b * LSEQ + l];
        tile[ty + i * 8][tx] = __expf(v - cm) * ci;
    }
    __syncthreads();
#pragma unroll
    for (int i = 0; i < 4; i++) {
        const int s = s0 + ty + i * 8;
        Pb[(long long)s * LSEQ + l0 + tx] = tile[tx][ty + i * 8];
    }
}

// ---------------- launch ----------------
extern "C" void kernel_launch(void* const* d_in, const int* in_sizes, int n_in,
                              void* d_out, int out_size) {
    const float* latents = (const float*)d_in[0];
    const float* tokens  = (const float*)d_in[1];
    const float* W_lat   = (const float*)d_in[2];
    const float* W_tok   = (const float*)d_in[3];
    const float* W_vlat  = (const float*)d_in[4];
    const float* W_vtok  = (const float*)d_in[5];
    const float* conv_w  = (const float*)d_in[6];
    const float* conv_b  = (const float*)d_in[7];
    float* out = (float*)d_out;

    float *wc, *tok, *rlat, *rtok, *vlat, *vtok, *smat, *pct, *rmax, *rinv, *cmax, *cinv;
    cudaGetSymbolAddress((void**)&wc,   g_Wc);
    cudaGetSymbolAddress((void**)&tok,  g_tok);
    cudaGetSymbolAddress((void**)&rlat, g_Rlat);
    cudaGetSymbolAddress((void**)&rtok, g_Rtok);
    cudaGetSymbolAddress((void**)&vlat, g_Vlat);
    cudaGetSymbolAddress((void**)&vtok, g_Vtok);
    cudaGetSymbolAddress((void**)&smat, g_S);
    cudaGetSymbolAddress((void**)&pct,  g_PcT);
    cudaGetSymbolAddress((void**)&rmax, g_rmax);
    cudaGetSymbolAddress((void**)&rinv, g_rinv);
    cudaGetSymbolAddress((void**)&cmax, g_cmax);
    cudaGetSymbolAddress((void**)&cinv, g_cinv);

    const long long UL = (long long)NB * LSEQ * DIM;
    const long long UT = (long long)NB * SSEQ * DIM;
    const long long CONCAT = UL + UT;

    k_prep_w<<<(DIM * KIN + 255) / 256, 256>>>(conv_w, wc);

    // conv as GEMM
    k_gemm_tc<0, 0><<<dim3(DIM / BN, (NB * SSEQ) / BM, 1), 256>>>(
        tokens, wc, tok, nullptr, KIN, KIN, KIN, DIM, 0, 0, 0, 0,
        1.f, conv_b, nullptr, 0);

    // projections
    k_gemm_tc<0, 0><<<dim3(DIM / BN, (NB * LSEQ) / BM, 1), 256>>>(
        latents, W_lat, rlat, nullptr, DIM, DIM, DIM, DIM, 0, 0, 0, 0,
        1.f, nullptr, nullptr, 0);
    k_gemm_tc<0, 0><<<dim3(DIM / BN, (NB * LSEQ) / BM, 1), 256>>>(
        latents, W_vlat, vlat, nullptr, DIM, DIM, DIM, DIM, 0, 0, 0, 0,
        1.f, nullptr, nullptr, 0);
    k_gemm_tc<0, 0><<<dim3(DIM / BN, (NB * SSEQ) / BM, 1), 256>>>(
        tok, W_tok, rtok, nullptr, DIM, DIM, DIM, DIM, 0, 0, 0, 0,
        1.f, nullptr, nullptr, 0);
    k_gemm_tc<0, 0><<<dim3(DIM / BN, (NB * SSEQ) / BM, 1), 256>>>(
        tok, W_vtok, vtok, nullptr, DIM, DIM, DIM, DIM, 0, 0, 0, 0,
        1.f, nullptr, nullptr, 0);

    // scores
    const float scale = 0.044194173824159216f;
    k_gemm_tc<0, 0><<<dim3(SSEQ / BN, LSEQ / BM, NB), 256>>>(
        rlat, rtok, smat, nullptr, DIM, DIM, DIM, SSEQ,
        (long long)LSEQ * DIM, (long long)SSEQ * DIM, (long long)LSEQ * SSEQ, 0,
        scale, nullptr, nullptr, 0);

    // softmax stats + apply
    k_row_stats<<<NB * LSEQ, 256>>>(smat, rmax, rinv);
    k_col_stats<<<dim3(SSEQ / 256, NB), 256>>>(smat, cmax, cinv);
    k_softmax_apply<<<dim3(SSEQ / 32, LSEQ / 32, NB), 256>>>(
        smat, pct, rmax, rinv, cmax, cinv);

    // delta_lat = Prow @ Vtok + latents
    k_gemm_tc<1, 1><<<dim3(DIM / BN, LSEQ / BM, NB), 256>>>(
        smat, vtok, out, out + CONCAT, SSEQ, SSEQ, DIM, DIM,
        (long long)LSEQ * SSEQ, (long long)SSEQ * DIM,
        (long long)LSEQ * DIM, (long long)(LSEQ + SSEQ) * DIM,
        1.f, nullptr, latents, (long long)LSEQ * DIM);

    // delta_tok = PcolT @ Vlat + tok
    k_gemm_tc<1, 1><<<dim3(DIM / BN, SSEQ / BM, NB), 256>>>(
        pct, vlat, out + UL, out + CONCAT + (long long)LSEQ * DIM, LSEQ, LSEQ, DIM, DIM,
        (long long)SSEQ * LSEQ, (long long)LSEQ * DIM,
        (long long)SSEQ * DIM, (long long)(LSEQ + SSEQ) * DIM,
        1.f, nullptr, tok, (long long)SSEQ * DIM);
}

// round 4
// speedup vs baseline: 3.3177x; 1.0286x over previous
#include <cuda_runtime.h>
#include <math.h>
#include <stdint.h>

// ---------------- problem constants ----------------
#define NB   8
#define LSEQ 1024
#define SSEQ 2048
#define DIM  512
#define TOKD 256
#define KIN  1280

// ---------------- scratch ----------------
__device__ __align__(256) float g_Wc  [DIM * KIN];          // conv weight, tf32-rounded
__device__ __align__(256) float g_Wr  [4 * DIM * DIM];      // 4 proj weights, tf32-rounded
__device__ __align__(256) float g_tok [NB * SSEQ * DIM];    // conv out, exact
__device__ __align__(256) float g_tokR[NB * SSEQ * DIM];    // conv out, rounded
__device__ __align__(256) float g_Rlat[NB * LSEQ * DIM];    // rounded
__device__ __align__(256) float g_Rtok[NB * SSEQ * DIM];    // rounded
__device__ __align__(256) float g_Vlat[NB * LSEQ * DIM];    // rounded
__device__ __align__(256) float g_Vtok[NB * SSEQ * DIM];    // rounded
__device__ __align__(256) float g_S   [NB * LSEQ * SSEQ];   // scores (exact), then Prow (rounded)
__device__ __align__(256) float g_PcT [NB * SSEQ * LSEQ];   // col-softmax transposed, rounded
__device__ __align__(256) float g_rmax[NB * LSEQ];
__device__ __align__(256) float g_rinv[NB * LSEQ];
__device__ __align__(256) float g_cmax[NB * SSEQ];
__device__ __align__(256) float g_cinv[NB * SSEQ];
__device__ __align__(256) float g_pmax[NB * 8 * SSEQ];
__device__ __align__(256) float g_psum[NB * 8 * SSEQ];

// ---------------- GEMM config ----------------
#define BM 128
#define BN 128
#define BK 16
#define P0 20
#define P1 132
#define STAGES 3
#define ASZ (BM * P0)          // floats per A stage

__device__ __forceinline__ uint32_t tf32r(float x) {
    uint32_t r;
    asm("cvt.rna.tf32.f32 %0, %1;" : "=r"(r) : "f"(x));
    return r;
}
__device__ __forceinline__ float tf32f(float x) { return __uint_as_float(tf32r(x)); }

__device__ __forceinline__ void mma_tf32(float c[4], const uint32_t a[4], const uint32_t b[2]) {
    asm volatile(
        "mma.sync.aligned.m16n8k8.row.col.f32.tf32.tf32.f32 "
        "{%0,%1,%2,%3}, {%4,%5,%6,%7}, {%8,%9}, {%0,%1,%2,%3};"
        : "+f"(c[0]), "+f"(c[1]), "+f"(c[2]), "+f"(c[3])
        : "r"(a[0]), "r"(a[1]), "r"(a[2]), "r"(a[3]), "r"(b[0]), "r"(b[1]));
}

__device__ __forceinline__ void cpasync16(void* dst, const void* src) {
    uint32_t d = (uint32_t)__cvta_generic_to_shared(dst);
    asm volatile("cp.async.cg.shared.global [%0], [%1], 16;" :: "r"(d), "l"(src));
}

// ---------------- TF32 tensor-core GEMM, 3-stage cp.async, 1 sync/tile ----------------
// C(M,N) = alpha * A(M,K) @ op(B)
//   BLAY=0: B is (N,K) k-contiguous     BLAY=1: B is (K,N) n-contiguous
//   CVTA/CVTB: apply cvt.rna at fragment load (for raw-f32 operands)
//   EPI=0: C = alpha*acc + bias[n] (exact)
//   EPI=1: v = acc + addend; store exact to C and C2
//   EPI=2: C = acc + bias (exact); C2 = tf32-rounded copy
//   EPI=3: C = tf32-rounded(alpha*acc)
template<int BLAY, int EPI, int CVTA, int CVTB>
__global__ __launch_bounds__(256, 2) void k_gemm_tc(
    const float* __restrict__ A, const float* __restrict__ B,
    float* __restrict__ C, float* __restrict__ C2,
    int K, int lda, int ldb, int ldc,
    long long sA, long long sB, long long sC, long long sC2,
    float alpha, const float* __restrict__ bias,
    const float* __restrict__ addend, long long sAdd)
{
    constexpr int BSZ = BLAY ? BK * P1 : BN * P0;
    extern __shared__ float sm[];
    float* As = sm;                      // STAGES * ASZ
    float* Bs = sm + STAGES * ASZ;       // STAGES * BSZ

    const long long z = blockIdx.z;
    A += z * sA;
    B += z * sB;
    C += z * sC;
    if (EPI == 1 || EPI == 2) C2 += z * sC2;
    if (EPI == 1) addend += z * sAdd;

    const int m0 = blockIdx.y * BM, n0 = blockIdx.x * BN;
    const int tid = threadIdx.x;
    const int wid = tid >> 5, lane = tid & 31;
    const int grp = lane >> 2, tig = lane & 3;
    const int wm = (wid >> 2) * 64, wn = (wid & 3) * 32;

    float acc[4][4][4];
#pragma unroll
    for (int i = 0; i < 4; i++)
#pragma unroll
        for (int j = 0; j < 4; j++)
#pragma unroll
            for (int r = 0; r < 4; r++) acc[i][j][r] = 0.f;

    auto loadTile = [&](int t, int buf) {
        const int k0 = t * BK;
        float* Ab = As + buf * ASZ;
        float* Bb = Bs + buf * BSZ;
#pragma unroll
        for (int i = 0; i < 2; i++) {
            int idx = i * 256 + tid;
            int row = idx >> 2, seg = idx & 3;
            cpasync16(Ab + row * P0 + seg * 4,
                      A + (long long)(m0 + row) * lda + k0 + seg * 4);
        }
        if (BLAY == 0) {
#pragma unroll
            for (int i = 0; i < 2; i++) {
                int idx = i * 256 + tid;
                int row = idx >> 2, seg = idx & 3;
                cpasync16(Bb + row * P0 + seg * 4,
                          B + (long long)(n0 + row) * ldb + k0 + seg * 4);
            }
        } else {
#pragma unroll
            for (int i = 0; i < 2; i++) {
                int idx = i * 256 + tid;
                int kr = idx >> 5, seg = idx & 31;
                cpasync16(Bb + kr * P1 + seg * 4,
                          B + (long long)(k0 + kr) * ldb + n0 + seg * 4);
            }
        }
        asm volatile("cp.async.commit_group;");
    };

    auto compute = [&](int buf) {
        const float* Af = As + buf * ASZ;
        const float* Bf = Bs + buf * BSZ;
#pragma unroll
        for (int ks = 0; ks < BK; ks += 8) {
            uint32_t af[4][4], bf[4][2];
#pragma unroll
            for (int mi = 0; mi < 4; mi++) {
                const int mr = wm + mi * 16 + grp;
                const float* p = Af + mr * P0 + ks + tig;
                if (CVTA) {
                    af[mi][0] = tf32r(p[0]);
                    af[mi][1] = tf32r(p[8 * P0]);
                    af[mi][2] = tf32r(p[4]);
                    af[mi][3] = tf32r(p[8 * P0 + 4]);
                } else {
                    af[mi][0] = __float_as_uint(p[0]);
                    af[mi][1] = __float_as_uint(p[8 * P0]);
                    af[mi][2] = __float_as_uint(p[4]);
                    af[mi][3] = __float_as_uint(p[8 * P0 + 4]);
                }
            }
#pragma unroll
            for (int ni = 0; ni < 4; ni++) {
                const int nc = wn + ni * 8 + grp;
                if (BLAY == 0) {
                    const float* p = Bf + nc * P0 + ks + tig;
                    if (CVTB) {
                        bf[ni][0] = tf32r(p[0]);
                        bf[ni][1] = tf32r(p[4]);
                    } else {
                        bf[ni][0] = __float_as_uint(p[0]);
                        bf[ni][1] = __float_as_uint(p[4]);
                    }
                } else {
                    const float* p = Bf + (ks + tig) * P1 + nc;
                    if (CVTB) {
                        bf[ni][0] = tf32r(p[0]);
                        bf[ni][1] = tf32r(p[4 * P1]);
                    } else {
                        bf[ni][0] = __float_as_uint(p[0]);
                        bf[ni][1] = __float_as_uint(p[4 * P1]);
                    }
                }
            }
#pragma unroll
            for (int mi = 0; mi < 4; mi++)
#pragma unroll
                for (int ni = 0; ni < 4; ni++)
                    mma_tf32(acc[mi][ni], af[mi], bf[ni]);
        }
    };

    const int tiles = K / BK;
#pragma unroll
    for (int s = 0; s < STAGES - 1; s++) loadTile(s, s);
    for (int t = 0; t < tiles; t++) {
        asm volatile("cp.async.wait_group %0;" :: "n"(STAGES - 2));
        __syncthreads();
        if (t + STAGES - 1 < tiles) loadTile(t + STAGES - 1, (t + STAGES - 1) % STAGES);
        compute(t % STAGES);
    }

    // epilogue
#pragma unroll
    for (int mi = 0; mi < 4; mi++) {
        const int r = m0 + wm + mi * 16 + grp;
#pragma unroll
        for (int ni = 0; ni < 4; ni++) {
            const int c = n0 + wn + ni * 8 + tig * 2;
            float2 v0 = {acc[mi][ni][0], acc[mi][ni][1]};
            float2 v1 = {acc[mi][ni][2], acc[mi][ni][3]};
            if (EPI == 0 || EPI == 2 || EPI == 3) {
                float bx = 0.f, by = 0.f;
                if ((EPI == 0 || EPI == 2) && bias) { bx = bias[c]; by = bias[c + 1]; }
                v0.x = alpha * v0.x + bx; v0.y = alpha * v0.y + by;
                v1.x = alpha * v1.x + bx; v1.y = alpha * v1.y + by;
                if (EPI == 3) {
                    v0.x = tf32f(v0.x); v0.y = tf32f(v0.y);
                    v1.x = tf32f(v1.x); v1.y = tf32f(v1.y);
                }
                *(float2*)(C + (long long)r * ldc + c) = v0;
                *(float2*)(C + (long long)(r + 8) * ldc + c) = v1;
                if (EPI == 2) {
                    float2 r0 = {tf32f(v0.x), tf32f(v0.y)};
                    float2 r1 = {tf32f(v1.x), tf32f(v1.y)};
                    *(float2*)(C2 + (long long)r * ldc + c) = r0;
                    *(float2*)(C2 + (long long)(r + 8) * ldc + c) = r1;
                }
            } else {   // EPI == 1
                float2 a0 = *(const float2*)(addend + (long long)r * ldc + c);
                float2 a1 = *(const float2*)(addend + (long long)(r + 8) * ldc + c);
                v0.x += a0.x; v0.y += a0.y;
                v1.x += a1.x; v1.y += a1.y;
                *(float2*)(C  + (long long)r * ldc + c) = v0;
                *(float2*)(C  + (long long)(r + 8) * ldc + c) = v1;
                *(float2*)(C2 + (long long)r * ldc + c) = v0;
                *(float2*)(C2 + (long long)(r + 8) * ldc + c) = v1;
            }
        }
    }
}

// ---------------- weight prep (both tf32-rounded) ----------------
__global__ void k_prep_w(const float* __restrict__ w, float* __restrict__ wc) {
    int i = blockIdx.x * 256 + threadIdx.x;
    if (i < DIM * KIN) {
        int e = i / KIN;
        int r = i - e * KIN;
        int t = r / TOKD;
        int c = r - t * TOKD;
        wc[i] = tf32f(w[e * KIN + c * 5 + t]);
    }
}
__global__ void k_round_w(const float* __restrict__ w0, const float* __restrict__ w1,
                          const float* __restrict__ w2, const float* __restrict__ w3,
                          float* __restrict__ out) {
    int i = blockIdx.x * 256 + threadIdx.x;
    if (i < DIM * DIM) {
        out[i]                 = tf32f(w0[i]);
        out[i + DIM * DIM]     = tf32f(w1[i]);
        out[i + 2 * DIM * DIM] = tf32f(w2[i]);
        out[i + 3 * DIM * DIM] = tf32f(w3[i]);
    }
}

// ---------------- softmax stats ----------------
__global__ void k_row_stats(const float* __restrict__ A,
                            float* __restrict__ rmax, float* __restrict__ rinv) {
    __shared__ float red[256];
    long long r = blockIdx.x;
    const float* row = A + r * SSEQ;
    int tid = threadIdx.x;
    float m = -1e30f;
    for (int c = tid; c < SSEQ; c += 256) m = fmaxf(m, row[c]);
    red[tid] = m; __syncthreads();
    for (int s = 128; s > 0; s >>= 1) {
        if (tid < s) red[tid] = fmaxf(red[tid], red[tid + s]);
        __syncthreads();
    }
    m = red[0];
    __syncthreads();
    float sum = 0.f;
    for (int c = tid; c < SSEQ; c += 256) sum += __expf(row[c] - m);
    red[tid] = sum; __syncthreads();
    for (int s = 128; s > 0; s >>= 1) {
        if (tid < s) red[tid] += red[tid + s];
        __syncthreads();
    }
    if (tid == 0) { rmax[r] = m; rinv[r] = 1.f / red[0]; }
}

// column stats: partial (max,sum) per 128-row l-chunk, then merge
__global__ void k_col_part(const float* __restrict__ A,
                           float* __restrict__ pmax, float* __restrict__ psum) {
    const int b = blockIdx.z, ch = blockIdx.y;
    const int s = blockIdx.x * 256 + threadIdx.x;
    const float* Ab = A + (long long)b * LSEQ * SSEQ + (long long)ch * 128 * SSEQ + s;
    float m = -1e30f, sum = 0.f;
#pragma unroll 4
    for (int l = 0; l < 128; l++) {
        float v = Ab[(long long)l * SSEQ];
        float mn = fmaxf(m, v);
        sum = sum * __expf(m - mn) + __expf(v - mn);
        m = mn;
    }
    pmax[(b * 8 + ch) * SSEQ + s] = m;
    psum[(b * 8 + ch) * SSEQ + s] = sum;
}
__global__ void k_col_comb(const float* __restrict__ pmax, const float* __restrict__ psum,
                           float* __restrict__ cmax, float* __restrict__ cinv) {
    const int b = blockIdx.y;
    const int s = blockIdx.x * 256 + threadIdx.x;
    float m = -1e30f;
#pragma unroll
    for (int c = 0; c < 8; c++) m = fmaxf(m, pmax[(b * 8 + c) * SSEQ + s]);
    float sum = 0.f;
#pragma unroll
    for (int c = 0; c < 8; c++)
        sum += psum[(b * 8 + c) * SSEQ + s] * __expf(pmax[(b * 8 + c) * SSEQ + s] - m);
    cmax[b * SSEQ + s] = m;
    cinv[b * SSEQ + s] = 1.f / sum;
}

// ---------------- apply both softmaxes: Prow in place (rounded), PcT transposed (rounded) ----------------
__global__ __launch_bounds__(256) void k_softmax_apply(
    float* __restrict__ A, float* __restrict__ PcT,
    const float* __restrict__ rmax, const float* __restrict__ rinv,
    const float* __restrict__ cmax, const float* __restrict__ cinv)
{
    __shared__ float tile[32][33];
    const int b = blockIdx.z;
    const int s0 = blockIdx.x * 32, l0 = blockIdx.y * 32;
    float* Ab = A + (long long)b * LSEQ * SSEQ;
    float* Pb = PcT + (long long)b * SSEQ * LSEQ;
    const int tx = threadIdx.x & 31, ty = threadIdx.x >> 5;

    const float cm = cmax[b * SSEQ + s0 + tx];
    const float ci = cinv[b * SSEQ + s0 + tx];
#pragma unroll
    for (int i = 0; i < 4; i++) {
        const int l = l0 + ty + i * 8;
        float v = Ab[(long long)l * SSEQ + s0 + tx];
        Ab[(long long)l * SSEQ + s0 + tx] = tf32f(__expf(v - rmax[b * LSEQ + l]) * rinv[b * LSEQ + l]);
        tile[ty + i * 8][tx] = tf32f(__expf(v - cm) * ci);
    }
    __syncthreads();
#pragma unroll
    for (int i = 0; i < 4; i++) {
        const int s = s0 + ty + i * 8;
        Pb[(long long)s * LSEQ + l0 + tx] = tile[tx][ty + i * 8];
    }
}

// ---------------- launch ----------------
extern "C" void kernel_launch(void* const* d_in, const int* in_sizes, int n_in,
                              void* d_out, int out_size) {
    const float* latents = (const float*)d_in[0];
    const float* tokens  = (const float*)d_in[1];
    const float* W_lat   = (const float*)d_in[2];
    const float* W_tok   = (const float*)d_in[3];
    const float* W_vlat  = (const float*)d_in[4];
    const float* W_vtok  = (const float*)d_in[5];
    const float* conv_w  = (const float*)d_in[6];
    const float* conv_b  = (const float*)d_in[7];
    float* out = (float*)d_out;

    float *wc, *wr, *tok, *tokR, *rlat, *rtok, *vlat, *vtok, *smat, *pct;
    float *rmax, *rinv, *cmax, *cinv, *pmax, *psum;
    cudaGetSymbolAddress((void**)&wc,   g_Wc);
    cudaGetSymbolAddress((void**)&wr,   g_Wr);
    cudaGetSymbolAddress((void**)&tok,  g_tok);
    cudaGetSymbolAddress((void**)&tokR, g_tokR);
    cudaGetSymbolAddress((void**)&rlat, g_Rlat);
    cudaGetSymbolAddress((void**)&rtok, g_Rtok);
    cudaGetSymbolAddress((void**)&vlat, g_Vlat);
    cudaGetSymbolAddress((void**)&vtok, g_Vtok);
    cudaGetSymbolAddress((void**)&smat, g_S);
    cudaGetSymbolAddress((void**)&pct,  g_PcT);
    cudaGetSymbolAddress((void**)&rmax, g_rmax);
    cudaGetSymbolAddress((void**)&rinv, g_rinv);
    cudaGetSymbolAddress((void**)&cmax, g_cmax);
    cudaGetSymbolAddress((void**)&cinv, g_cinv);
    cudaGetSymbolAddress((void**)&pmax, g_pmax);
    cudaGetSymbolAddress((void**)&psum, g_psum);

    // dynamic smem sizes and attributes (per instantiation)
    const int SM_B0 = STAGES * (ASZ + BN * P0) * 4;   // 61440
    const int SM_B1 = STAGES * (ASZ + BK * P1) * 4;   // 56064
    cudaFuncSetAttribute(k_gemm_tc<0, 2, 1, 0>, cudaFuncAttributeMaxDynamicSharedMemorySize, SM_B0);
    cudaFuncSetAttribute(k_gemm_tc<0, 3, 1, 0>, cudaFuncAttributeMaxDynamicSharedMemorySize, SM_B0);
    cudaFuncSetAttribute(k_gemm_tc<0, 3, 0, 0>, cudaFuncAttributeMaxDynamicSharedMemorySize, SM_B0);
    cudaFuncSetAttribute(k_gemm_tc<0, 0, 0, 0>, cudaFuncAttributeMaxDynamicSharedMemorySize, SM_B0);
    cudaFuncSetAttribute(k_gemm_tc<1, 1, 0, 0>, cudaFuncAttributeMaxDynamicSharedMemorySize, SM_B1);

    const long long UL = (long long)NB * LSEQ * DIM;
    const long long UT = (long long)NB * SSEQ * DIM;
    const long long CONCAT = UL + UT;

    k_prep_w<<<(DIM * KIN + 255) / 256, 256>>>(conv_w, wc);
    k_round_w<<<(DIM * DIM + 255) / 256, 256>>>(W_lat, W_tok, W_vlat, W_vtok, wr);

    // conv as GEMM: tok (exact) + tokR (rounded)
    k_gemm_tc<0, 2, 1, 0><<<dim3(DIM / BN, (NB * SSEQ) / BM, 1), 256, SM_B0>>>(
        tokens, wc, tok, tokR, KIN, KIN, KIN, DIM, 0, 0, 0, 0,
        1.f, conv_b, nullptr, 0);

    // projections -> rounded outputs
    k_gemm_tc<0, 3, 1, 0><<<dim3(DIM / BN, (NB * LSEQ) / BM, 1), 256, SM_B0>>>(
        latents, wr + 0 * DIM * DIM, rlat, nullptr, DIM, DIM, DIM, DIM, 0, 0, 0, 0,
        1.f, nullptr, nullptr, 0);
    k_gemm_tc<0, 3, 1, 0><<<dim3(DIM / BN, (NB * LSEQ) / BM, 1), 256, SM_B0>>>(
        latents, wr + 2 * DIM * DIM, vlat, nullptr, DIM, DIM, DIM, DIM, 0, 0, 0, 0,
        1.f, nullptr, nullptr, 0);
    k_gemm_tc<0, 3, 0, 0><<<dim3(DIM / BN, (NB * SSEQ) / BM, 1), 256, SM_B0>>>(
        tokR, wr + 1 * DIM * DIM, rtok, nullptr, DIM, DIM, DIM, DIM, 0, 0, 0, 0,
        1.f, nullptr, nullptr, 0);
    k_gemm_tc<0, 3, 0, 0><<<dim3(DIM / BN, (NB * SSEQ) / BM, 1), 256, SM_B0>>>(
        tokR, wr + 3 * DIM * DIM, vtok, nullptr, DIM, DIM, DIM, DIM, 0, 0, 0, 0,
        1.f, nullptr, nullptr, 0);

    // scores (exact output)
    const float scale = 0.044194173824159216f;
    k_gemm_tc<0, 0, 0, 0><<<dim3(SSEQ / BN, LSEQ / BM, NB), 256, SM_B0>>>(
        rlat, rtok, smat, nullptr, DIM, DIM, DIM, SSEQ,
        (long long)LSEQ * DIM, (long long)SSEQ * DIM, (long long)LSEQ * SSEQ, 0,
        scale, nullptr, nullptr, 0);

    // softmax stats + apply
    k_row_stats<<<NB * LSEQ, 256>>>(smat, rmax, rinv);
    k_col_part<<<dim3(SSEQ / 256, 8, NB), 256>>>(smat, pmax, psum);
    k_col_comb<<<dim3(SSEQ / 256, NB), 256>>>(pmax, psum, cmax, cinv);
    k_softmax_apply<<<dim3(SSEQ / 32, LSEQ / 32, NB), 256>>>(
        smat, pct, rmax, rinv, cmax, cinv);

    // delta_lat = Prow @ Vtok + latents
    k_gemm_tc<1, 1, 0, 0><<<dim3(DIM / BN, LSEQ / BM, NB), 256, SM_B1>>>(
        smat, vtok, out, out + CONCAT, SSEQ, SSEQ, DIM, DIM,
        (long long)LSEQ * SSEQ, (long long)SSEQ * DIM,
        (long long)LSEQ * DIM, (long long)(LSEQ + SSEQ) * DIM,
        1.f, nullptr, latents, (long long)LSEQ * DIM);

    // delta_tok = PcolT @ Vlat + tok
    k_gemm_tc<1, 1, 0, 0><<<dim3(DIM / BN, SSEQ / BM, NB), 256, SM_B1>>>(
        pct, vlat, out + UL, out + CONCAT + (long long)LSEQ * DIM, LSEQ, LSEQ, DIM, DIM,
        (long long)SSEQ * LSEQ, (long long)LSEQ * DIM,
        (long long)SSEQ * DIM, (long long)(LSEQ + SSEQ) * DIM,
        1.f, nullptr, tok, (long long)SSEQ * DIM);
}